// round 4
// baseline (speedup 1.0000x reference)
#include <cuda_runtime.h>
#include <cuda_fp16.h>
#include <stdint.h>

// SpikeFP16Adder: A,B are [N,16] float32 arrays of 0/1 spikes (MSB-first fp16
// bit encodings). Output [N,16] float32 spikes of the fp16 sum with the
// reference's (XLA-on-aarch64, f32-promotion) semantics:
//   - A NaN  -> quiet(A)  (sign+payload preserved, bit9 set)
//   - else B NaN -> quiet(B)
//   - Inf + (-Inf) -> 0x7E00 (f32 default NaN narrowed to fp16)
//   - everything else: IEEE RNE == hardware __hadd (double rounding via f32
//     is exact for addition since 24 >= 2*11+2; subnormals handled by HW)
//
// Streaming kernel: 192 B HBM traffic per element.

__global__ void __launch_bounds__(256)
spike_fp16_add_kernel(const uint4* __restrict__ A,
                      const uint4* __restrict__ B,
                      float4* __restrict__ O,
                      int n_elems) {
    int i = blockIdx.x * blockDim.x + threadIdx.x;
    if (i >= n_elems) return;

    unsigned ua = 0u, ub = 0u;

    // 16 spike floats per operand = 4 uint4 loads. Spikes are exactly 0.0f or
    // 1.0f, so bit(value) = (float_bits >> 23) & 1 (exponent LSB of 1.0f).
#pragma unroll
    for (int j = 0; j < 4; ++j) {
        uint4 va = A[4 * i + j];
        uint4 vb = B[4 * i + j];
        const int base = 15 - 4 * j;
        ua |= ((va.x >> 23) & 1u) << (base - 0);
        ua |= ((va.y >> 23) & 1u) << (base - 1);
        ua |= ((va.z >> 23) & 1u) << (base - 2);
        ua |= ((va.w >> 23) & 1u) << (base - 3);
        ub |= ((vb.x >> 23) & 1u) << (base - 0);
        ub |= ((vb.y >> 23) & 1u) << (base - 1);
        ub |= ((vb.z >> 23) & 1u) << (base - 2);
        ub |= ((vb.w >> 23) & 1u) << (base - 3);
    }

    // Normal-path add via hardware HADD.
    unsigned hw = (unsigned)__half_as_ushort(
        __hadd(__ushort_as_half((unsigned short)ua),
               __ushort_as_half((unsigned short)ub)));

    unsigned mag_a = ua & 0x7FFFu;
    unsigned mag_b = ub & 0x7FFFu;
    bool a_nan = mag_a > 0x7C00u;
    bool b_nan = mag_b > 0x7C00u;

    // f32-promotion NaN rule: operand order only, quiet the winner.
    unsigned nan_sel = (a_nan ? ua : ub) | 0x0200u;

    // Inf + (-Inf): default NaN after promotion round-trip.
    bool inf_inf = (mag_a == 0x7C00u) && (mag_b == 0x7C00u) &&
                   (((ua ^ ub) & 0x8000u) != 0u);

    unsigned us = (a_nan | b_nan) ? nan_sel : (inf_inf ? 0x7E00u : hw);

#pragma unroll
    for (int j = 0; j < 4; ++j) {
        const int base = 15 - 4 * j;
        float4 o;
        o.x = ((us >> (base - 0)) & 1u) ? 1.0f : 0.0f;
        o.y = ((us >> (base - 1)) & 1u) ? 1.0f : 0.0f;
        o.z = ((us >> (base - 2)) & 1u) ? 1.0f : 0.0f;
        o.w = ((us >> (base - 3)) & 1u) ? 1.0f : 0.0f;
        O[4 * i + j] = o;
    }
}

extern "C" void kernel_launch(void* const* d_in, const int* in_sizes, int n_in,
                              void* d_out, int out_size) {
    const uint4* A = (const uint4*)d_in[0];
    const uint4* B = (const uint4*)d_in[1];
    float4* O = (float4*)d_out;

    int n_elems = in_sizes[0] / 16;  // N rows of 16 spikes
    int threads = 256;
    int blocks = (n_elems + threads - 1) / threads;
    spike_fp16_add_kernel<<<blocks, threads>>>(A, B, O, n_elems);
}

// round 5
// speedup vs baseline: 1.0684x; 1.0684x over previous
#include <cuda_runtime.h>
#include <cuda_fp16.h>
#include <stdint.h>

// SpikeFP16Adder, warp-transposed coalesced version.
//
// A,B: [N,16] float32 spikes (0.0/1.0), MSB-first fp16 bit encodings.
// Out: [N,16] float32 spikes of the fp16 sum with the reference's
// (XLA-on-aarch64, f32-promotion) semantics:
//   - A NaN -> quiet(A); else B NaN -> quiet(B)   (sign+payload kept, bit9 set)
//   - Inf + (-Inf) -> 0x7E00
//   - else: IEEE RNE == hardware __hadd
//
// Layout: one uint4/float4 (= 4 spikes = one quarter of an element) per
// thread -> perfectly coalesced 128-bit loads/stores (4 full lines per warp
// request instead of 16 partially-consumed ones). The 16-bit operand is
// assembled across the 4-lane group with a 2-step butterfly shuffle-OR.
// Nibble conversion uses a 3-FFMA Horner chain (FFMA-imm, rt=1) + F2I.

__global__ void __launch_bounds__(256)
spike_fp16_add_kernel(const float4* __restrict__ A,
                      const float4* __restrict__ B,
                      float4* __restrict__ O,
                      int n_vec) {
    int idx = blockIdx.x * blockDim.x + threadIdx.x;
    if (idx >= n_vec) return;   // never taken for partial warps: n_vec % 256 == 0

    float4 a = A[idx];
    float4 b = B[idx];

    // Quarter q of the element; this thread's nibble sits at bits [sh+3 .. sh].
    unsigned q  = (unsigned)idx & 3u;
    unsigned sh = 12u - 4u * q;

    // Spikes are exactly 0.0f/1.0f -> Horner chain is exact integer math in fp32.
    float fa = ((a.x * 2.0f + a.y) * 2.0f + a.z) * 2.0f + a.w;
    float fb = ((b.x * 2.0f + b.y) * 2.0f + b.z) * 2.0f + b.w;
    unsigned na = ((unsigned)fa) << sh;
    unsigned nb = ((unsigned)fb) << sh;

    // Butterfly OR over the 4-lane group: every lane ends with the full word.
    na |= __shfl_xor_sync(0xFFFFFFFFu, na, 1);
    na |= __shfl_xor_sync(0xFFFFFFFFu, na, 2);
    nb |= __shfl_xor_sync(0xFFFFFFFFu, nb, 1);
    nb |= __shfl_xor_sync(0xFFFFFFFFu, nb, 2);

    unsigned ua = na, ub = nb;

    // Normal path: hardware HADD (exact IEEE RNE incl. subnormals).
    unsigned hw = (unsigned)__half_as_ushort(
        __hadd(__ushort_as_half((unsigned short)ua),
               __ushort_as_half((unsigned short)ub)));

    unsigned mag_a = ua & 0x7FFFu;
    unsigned mag_b = ub & 0x7FFFu;
    bool a_nan = mag_a > 0x7C00u;
    bool b_nan = mag_b > 0x7C00u;

    // f32-promotion NaN rule: operand order only, quiet the winner.
    unsigned nan_sel = (a_nan ? ua : ub) | 0x0200u;

    // Inf + (-Inf) -> default NaN after the promotion round-trip.
    bool inf_inf = (mag_a == 0x7C00u) && (mag_b == 0x7C00u) &&
                   (((ua ^ ub) & 0x8000u) != 0u);

    unsigned us = (a_nan | b_nan) ? nan_sel : (inf_inf ? 0x7E00u : hw);

    // Emit this thread's quarter: spike float bits = bit * 0x3F800000.
    float4 o;
    o.x = __uint_as_float(((us >> (sh + 3u)) & 1u) * 0x3F800000u);
    o.y = __uint_as_float(((us >> (sh + 2u)) & 1u) * 0x3F800000u);
    o.z = __uint_as_float(((us >> (sh + 1u)) & 1u) * 0x3F800000u);
    o.w = __uint_as_float(((us >> (sh + 0u)) & 1u) * 0x3F800000u);
    O[idx] = o;
}

extern "C" void kernel_launch(void* const* d_in, const int* in_sizes, int n_in,
                              void* d_out, int out_size) {
    const float4* A = (const float4*)d_in[0];
    const float4* B = (const float4*)d_in[1];
    float4* O = (float4*)d_out;

    int n_vec = in_sizes[0] / 4;  // number of float4 quarters (= 4 per element)
    int threads = 256;
    int blocks = (n_vec + threads - 1) / threads;
    spike_fp16_add_kernel<<<blocks, threads>>>(A, B, O, n_vec);
}